// round 9
// baseline (speedup 1.0000x reference)
#include <cuda_runtime.h>
#include <cuda_bf16.h>
#include <cstdint>

// ---------------- problem constants ----------------
constexpr int Bz = 4, Cn = 128, Hh = 128, Wd = 128;
constexpr int HW = Hh * Wd;       // 16384
constexpr int P  = Bz * HW;       // 65536 pixels
constexpr int NCH = 256, CL = 64; // scan: 256 chunks of 64 steps

// ---------------- scratch ----------------
__device__ float g_xin [P * Cn];
__device__ float g_xc  [P * Cn];
__device__ float g_off [P * 16];
__device__ float g_xd  [P * Cn];
__device__ float g_ab  [P * Cn * 2];   // interleaved (a, bx)
__device__ float g_C   [P];
__device__ float g_y   [P * Cn];
__device__ float g_As  [Bz * NCH * Cn];
__device__ float g_Bs  [Bz * NCH * Cn];
__device__ float g_hin [Bz * NCH * Cn];
// bf16 hi/lo weight images, row-major [o][c]
__device__ __align__(16) unsigned short g_wbhi_in [16384];
__device__ __align__(16) unsigned short g_wblo_in [16384];
__device__ __align__(16) unsigned short g_wbhi_out[16384];
__device__ __align__(16) unsigned short g_wblo_out[16384];

__device__ __forceinline__ uint32_t smem_to_u32(const void* p) {
    uint32_t a;
    asm("{ .reg .u64 t; cvta.to.shared.u64 t, %1; cvt.u32.u64 %0, t; }" : "=r"(a) : "l"(p));
    return a;
}

// smem tile layout: row stride 256B (128 bf16), 16B chunks XOR-swizzled by row
__device__ __forceinline__ uint32_t sw_off(int row, int k) {
    int chunk = k >> 3;
    int swch = (chunk & 8) | ((chunk ^ row) & 7);
    return (uint32_t)(row * 256 + swch * 16 + (k & 7) * 2);
}

#define LDSM_X4(r0, r1, r2, r3, addr) \
    asm volatile("ldmatrix.sync.aligned.m8n8.x4.shared.b16 {%0,%1,%2,%3}, [%4];" \
                 : "=r"(r0), "=r"(r1), "=r"(r2), "=r"(r3) : "r"(addr))
#define MMA16816(d, a, b0v, b1v) \
    asm volatile("mma.sync.aligned.m16n8k16.row.col.f32.bf16.bf16.f32 " \
                 "{%0,%1,%2,%3}, {%4,%5,%6,%7}, {%8,%9}, {%0,%1,%2,%3};" \
                 : "+f"((d)[0]), "+f"((d)[1]), "+f"((d)[2]), "+f"((d)[3]) \
                 : "r"((a)[0]), "r"((a)[1]), "r"((a)[2]), "r"((a)[3]), "r"(b0v), "r"(b1v))

// dyn smem layout for GEMM kernels (128KB)
constexpr int SM_A_HI = 0, SM_A_LO = 32768, SM_B_HI = 65536, SM_B_LO = 98304;
constexpr int SM_GEMM = 131072;

// =====================================================================
// K0: split weights into bf16 hi/lo (row-major [o][c])
// =====================================================================
__global__ void k_prep_w(const float* __restrict__ inw, const float* __restrict__ outw) {
    int idx = blockIdx.x * 256 + threadIdx.x;   // 32768 total
    int which = idx >> 14, rem = idx & 16383;
    float v = (which ? outw : inw)[rem];
    __nv_bfloat16 h = __float2bfloat16(v);
    __nv_bfloat16 l = __float2bfloat16(v - __bfloat162float(h));
    if (which) { g_wbhi_out[rem] = __bfloat16_as_ushort(h); g_wblo_out[rem] = __bfloat16_as_ushort(l); }
    else       { g_wbhi_in [rem] = __bfloat16_as_ushort(h); g_wblo_in [rem] = __bfloat16_as_ushort(l); }
}

// =====================================================================
// core mma loop: warp tile 16M x 64N, K=128, 3-term hi/lo bf16
// =====================================================================
__device__ __forceinline__ void gemm_mma16(uint32_t sAhi, uint32_t sAlo,
                                           uint32_t sBhi, uint32_t sBlo,
                                           int lane, int m0, int n0,
                                           float acc[8][4]) {
    const int aRow = lane & 15;
    const int aK   = (lane >> 4) << 3;
    const int bRow = (lane & 7) | (((lane >> 4) & 1) << 3);
    const int bK   = ((lane >> 3) & 1) << 3;
#pragma unroll
    for (int kk = 0; kk < 128; kk += 16) {
        uint32_t ah[4], al[4], bh[4][4], bl[4][4];
        {
            uint32_t off = sw_off(m0 + aRow, kk + aK);
            LDSM_X4(ah[0], ah[1], ah[2], ah[3], sAhi + off);
            LDSM_X4(al[0], al[1], al[2], al[3], sAlo + off);
        }
#pragma unroll
        for (int nq = 0; nq < 4; nq++) {
            uint32_t off = sw_off(n0 + nq * 16 + bRow, kk + bK);
            LDSM_X4(bh[nq][0], bh[nq][1], bh[nq][2], bh[nq][3], sBhi + off);
            LDSM_X4(bl[nq][0], bl[nq][1], bl[nq][2], bl[nq][3], sBlo + off);
        }
#pragma unroll
        for (int nq = 0; nq < 4; nq++)
#pragma unroll
            for (int hf = 0; hf < 2; hf++) {
                float* d = acc[nq * 2 + hf];
                MMA16816(d, ah, bh[nq][hf * 2], bh[nq][hf * 2 + 1]);
                MMA16816(d, al, bh[nq][hf * 2], bh[nq][hf * 2 + 1]);
                MMA16816(d, ah, bl[nq][hf * 2], bl[nq][hf * 2 + 1]);
            }
    }
}

template<int NT>
__device__ __forceinline__ void copy_weights_sw(char* smem, const unsigned short* ghi,
                                                const unsigned short* glo, int t) {
    const uint4* shi = (const uint4*)ghi;
    const uint4* slo = (const uint4*)glo;
#pragma unroll
    for (int i = t; i < 2048; i += NT) {
        int row = i >> 4, chunk = i & 15;
        uint32_t doff = row * 256 + ((((chunk ^ row) & 7) | (chunk & 8)) << 4);
        *(uint4*)(smem + SM_B_HI + doff) = shi[i];
        *(uint4*)(smem + SM_B_LO + doff) = slo[i];
    }
}

// reduce 16 lane-distributed partials across a warp; output o lands on lane o (o<16).
__device__ __forceinline__ float reduce16_to_lane(float* v, int lane) {
#pragma unroll
    for (int j = 0; j < 16; j++) v[j] += __shfl_xor_sync(0xffffffffu, v[j], 16);
    float c8[8];
    const bool h8 = (lane & 8) != 0;
#pragma unroll
    for (int k = 0; k < 8; k++) {
        float send = h8 ? v[k] : v[k + 8];
        float keep = h8 ? v[k + 8] : v[k];
        c8[k] = keep + __shfl_xor_sync(0xffffffffu, send, 8);
    }
    float c4[4];
    const bool h4 = (lane & 4) != 0;
#pragma unroll
    for (int k = 0; k < 4; k++) {
        float send = h4 ? c8[k] : c8[k + 4];
        float keep = h4 ? c8[k + 4] : c8[k];
        c4[k] = keep + __shfl_xor_sync(0xffffffffu, send, 4);
    }
    float c2[2];
    const bool h2 = (lane & 2) != 0;
#pragma unroll
    for (int k = 0; k < 2; k++) {
        float send = h2 ? c4[k] : c4[k + 2];
        float keep = h2 ? c4[k + 2] : c4[k];
        c2[k] = keep + __shfl_xor_sync(0xffffffffu, send, 2);
    }
    const bool h1 = (lane & 1) != 0;
    float send = h1 ? c2[0] : c2[1];
    float keep = h1 ? c2[1] : c2[0];
    return keep + __shfl_xor_sync(0xffffffffu, send, 1);
}

// =====================================================================
// K1: in_proj GEMM.  x (B,C,HW) -> xin channels-last (p,c)
// =====================================================================
__global__ void __launch_bounds__(512) k_in_proj(const float* __restrict__ x) {
    extern __shared__ char smem[];
    uint32_t sb = smem_to_u32(smem);
    const int t = threadIdx.x, lane = t & 31, warp = t >> 5;
    const int p0 = blockIdx.x * 128, b = p0 >> 14, hw0 = p0 & 16383;

    copy_weights_sw<512>(smem, g_wbhi_in, g_wblo_in, t);
    for (int i = t; i < 16384; i += 512) {
        int c = i >> 7, m = i & 127;
        float v = x[(size_t)(b * 128 + c) * HW + hw0 + m];
        __nv_bfloat16 h = __float2bfloat16(v);
        __nv_bfloat16 l = __float2bfloat16(v - __bfloat162float(h));
        uint32_t off = sw_off(m, c);
        *(unsigned short*)(smem + SM_A_HI + off) = __bfloat16_as_ushort(h);
        *(unsigned short*)(smem + SM_A_LO + off) = __bfloat16_as_ushort(l);
    }
    __syncthreads();

    float acc[8][4];
#pragma unroll
    for (int j = 0; j < 8; j++)
#pragma unroll
        for (int q = 0; q < 4; q++) acc[j][q] = 0.f;

    const int m0 = (warp >> 1) * 16, n0 = (warp & 1) * 64;
    gemm_mma16(sb + SM_A_HI, sb + SM_A_LO, sb + SM_B_HI, sb + SM_B_LO, lane, m0, n0, acc);

#pragma unroll
    for (int ni = 0; ni < 8; ni++) {
        int row = m0 + (lane >> 2);
        int col = n0 + ni * 8 + (lane & 3) * 2;
        *(float2*)&g_xin[(size_t)(p0 + row) * 128 + col] =
            make_float2(acc[ni][0], acc[ni][1]);
        *(float2*)&g_xin[(size_t)(p0 + row + 8) * 128 + col] =
            make_float2(acc[ni][2], acc[ni][3]);
    }
}

// =====================================================================
// K2: depthwise 3x3 conv + bias + SiLU. WARP = 4 consecutive pixels.
// =====================================================================
__global__ void __launch_bounds__(256) k_dwsilu(const float* __restrict__ w,
                                                const float* __restrict__ bias) {
    __shared__ float sw[9 * 128];
    __shared__ float sb2[128];
    const int t = threadIdx.x;
    for (int i = t; i < 1152; i += 256) {
        int c = i / 9, k = i - c * 9;
        sw[k * 128 + c] = w[i];
    }
    if (t < 128) sb2[t] = bias[t];
    __syncthreads();

    const int warp = t >> 5, lane = t & 31, c0 = lane * 4;
    const int p0 = blockIdx.x * 32 + warp * 4;
    const int b = p0 >> 14, hw = p0 & 16383, yy = hw >> 7, xx0 = hw & 127;

    float4 bv = *(const float4*)&sb2[c0];
    float4 acc[4] = {bv, bv, bv, bv};
#pragma unroll
    for (int ky = 0; ky < 3; ky++) {
        int yv = yy + ky - 1;
        if ((unsigned)yv >= (unsigned)Hh) continue;
        const float* rowb = &g_xin[(size_t)(b * HW + yv * Wd) * Cn + c0];
        float4 v[6];
#pragma unroll
        for (int col = 0; col < 6; col++) {
            int xv = xx0 - 1 + col;
            v[col] = ((unsigned)xv < (unsigned)Wd) ? *(const float4*)&rowb[(size_t)xv * Cn]
                                                   : make_float4(0.f, 0.f, 0.f, 0.f);
        }
        float4 wv[3];
#pragma unroll
        for (int kx = 0; kx < 3; kx++) wv[kx] = *(const float4*)&sw[(ky * 3 + kx) * 128 + c0];
#pragma unroll
        for (int j = 0; j < 4; j++)
#pragma unroll
            for (int kx = 0; kx < 3; kx++) {
                float4 vv = v[j + kx];
                acc[j].x += wv[kx].x * vv.x; acc[j].y += wv[kx].y * vv.y;
                acc[j].z += wv[kx].z * vv.z; acc[j].w += wv[kx].w * vv.w;
            }
    }
#pragma unroll
    for (int j = 0; j < 4; j++) {
        float4 r;
        r.x = acc[j].x / (1.f + __expf(-acc[j].x));
        r.y = acc[j].y / (1.f + __expf(-acc[j].y));
        r.z = acc[j].z / (1.f + __expf(-acc[j].z));
        r.w = acc[j].w / (1.f + __expf(-acc[j].w));
        *(float4*)&g_xc[(size_t)(p0 + j) * Cn + c0] = r;
    }
}

__device__ __forceinline__ float softplusf(float x) {
    return fmaxf(x, 0.f) + log1pf(__expf(-fabsf(x)));
}

// =====================================================================
// K3: dwconv(dw_w) -> LN -> GELU -> offsets.  WARP = 4 pixels.
// =====================================================================
__global__ void __launch_bounds__(256) k_dw2_off(const float* __restrict__ w,
                          const float* __restrict__ bias,
                          const float* __restrict__ lng, const float* __restrict__ lnb,
                          const float* __restrict__ offw, const float* __restrict__ offb) {
    __shared__ float sw[9 * 128];
    __shared__ float sb[128], sg[128], sbt[128];
    __shared__ float sofw[16 * 128];
    __shared__ float sofb[16];
    const int t = threadIdx.x;
    for (int i = t; i < 1152; i += 256) {
        int c = i / 9, k = i - c * 9;
        sw[k * 128 + c] = w[i];
    }
    for (int i = t; i < 2048; i += 256) sofw[i] = offw[i];
    if (t < 128) { sb[t] = bias[t]; sg[t] = lng[t]; sbt[t] = lnb[t]; }
    if (t < 16) sofb[t] = offb[t];
    __syncthreads();

    const int warp = t >> 5, lane = t & 31, c0 = lane * 4;
    const int p0 = blockIdx.x * 32 + warp * 4;
    const int b = p0 >> 14, hw = p0 & 16383, yy = hw >> 7, xx0 = hw & 127;

    // dwconv + bias, 4 pixels with horizontal tap reuse
    float4 bv = *(const float4*)&sb[c0];
    float4 acc[4] = {bv, bv, bv, bv};
#pragma unroll
    for (int ky = 0; ky < 3; ky++) {
        int yv = yy + ky - 1;
        if ((unsigned)yv >= (unsigned)Hh) continue;
        const float* rowb = &g_xc[(size_t)(b * HW + yv * Wd) * Cn + c0];
        float4 v[6];
#pragma unroll
        for (int col = 0; col < 6; col++) {
            int xv = xx0 - 1 + col;
            v[col] = ((unsigned)xv < (unsigned)Wd) ? *(const float4*)&rowb[(size_t)xv * Cn]
                                                   : make_float4(0.f, 0.f, 0.f, 0.f);
        }
        float4 wv[3];
#pragma unroll
        for (int kx = 0; kx < 3; kx++) wv[kx] = *(const float4*)&sw[(ky * 3 + kx) * 128 + c0];
#pragma unroll
        for (int j = 0; j < 4; j++)
#pragma unroll
            for (int kx = 0; kx < 3; kx++) {
                float4 vv = v[j + kx];
                acc[j].x += wv[kx].x * vv.x; acc[j].y += wv[kx].y * vv.y;
                acc[j].z += wv[kx].z * vv.z; acc[j].w += wv[kx].w * vv.w;
            }
    }

    const float4 gl = *(const float4*)&sg[c0];
    const float4 bl = *(const float4*)&sbt[c0];
    // per-pixel: LN -> GELU -> offset matvec (merged loop to bound registers)
#pragma unroll
    for (int j = 0; j < 4; j++) {
        float s1 = acc[j].x + acc[j].y + acc[j].z + acc[j].w;
        float s2 = acc[j].x * acc[j].x + acc[j].y * acc[j].y
                 + acc[j].z * acc[j].z + acc[j].w * acc[j].w;
#pragma unroll
        for (int o = 16; o; o >>= 1) {
            s1 += __shfl_xor_sync(0xffffffffu, s1, o);
            s2 += __shfl_xor_sync(0xffffffffu, s2, o);
        }
        const float m = s1 * (1.f / 128.f);
        const float rs = rsqrtf(s2 * (1.f / 128.f) - m * m + 1e-6f);
        float xn0 = (acc[j].x - m) * rs * gl.x + bl.x;
        float xn1 = (acc[j].y - m) * rs * gl.y + bl.y;
        float xn2 = (acc[j].z - m) * rs * gl.z + bl.z;
        float xn3 = (acc[j].w - m) * rs * gl.w + bl.w;
        float u0 = 0.5f * xn0 * (1.f + erff(xn0 * 0.70710678118654752f));
        float u1 = 0.5f * xn1 * (1.f + erff(xn1 * 0.70710678118654752f));
        float u2 = 0.5f * xn2 * (1.f + erff(xn2 * 0.70710678118654752f));
        float u3 = 0.5f * xn3 * (1.f + erff(xn3 * 0.70710678118654752f));

        float ov[16];
#pragma unroll
        for (int o = 0; o < 16; o++) {
            float4 wv = *(const float4*)&sofw[o * 128 + c0];
            ov[o] = u0 * wv.x + u1 * wv.y + u2 * wv.z + u3 * wv.w;
        }
        float r = reduce16_to_lane(ov, lane);
        if (lane < 16) g_off[(p0 + j) * 16 + lane] = r + sofb[lane];
    }
}

// =====================================================================
// K4: DCNv3 sample + x_dbl + delta precompute.  WARP PER PIXEL.
// writes interleaved (a, bx) pairs
// =====================================================================
__global__ void __launch_bounds__(256) k_dcn_delta(const float* __restrict__ xpw,
                            const float* __restrict__ dtw, const float* __restrict__ dtb,
                            const float* __restrict__ alog) {
    __shared__ float sxp[10 * 128];
    const int t = threadIdx.x;
    for (int i = t; i < 1280; i += 256) sxp[i] = xpw[i];
    __syncthreads();

    const int p = blockIdx.x * 8 + (t >> 5);
    const int lane = t & 31, c0 = lane * 4;
    const int b = p >> 14, hw = p & 16383, yy = hw >> 7, xx = hw & 127;
    const int g = lane >> 2;

    const float ox = g_off[p * 16 + 2 * g];
    const float oy = g_off[p * 16 + 2 * g + 1];
    const float px = (float)xx + ox, py = (float)yy + oy;
    const float x0 = floorf(px), y0 = floorf(py);
    const float wx = px - x0, wy = py - y0;
    float4 xd = make_float4(0.f, 0.f, 0.f, 0.f);
#pragma unroll
    for (int dy = 0; dy < 2; dy++) {
#pragma unroll
        for (int dx = 0; dx < 2; dx++) {
            float yif = y0 + (float)dy, xif = x0 + (float)dx;
            float wgt = (dy ? wy : 1.f - wy) * (dx ? wx : 1.f - wx);
            bool valid = (yif >= 0.f) && (yif < (float)Hh) && (xif >= 0.f) && (xif < (float)Wd);
            wgt = valid ? wgt : 0.f;
            int yi = (int)fminf(fmaxf(yif, 0.f), (float)(Hh - 1));
            int xi = (int)fminf(fmaxf(xif, 0.f), (float)(Wd - 1));
            float4 v = *(const float4*)&g_xc[(size_t)(b * HW + yi * Wd + xi) * Cn + c0];
            xd.x += v.x * wgt; xd.y += v.y * wgt; xd.z += v.z * wgt; xd.w += v.w * wgt;
        }
    }
    *(float4*)&g_xd[(size_t)p * Cn + c0] = xd;

    float xb[10];
#pragma unroll
    for (int r = 0; r < 10; r++) {
        float4 wv = *(const float4*)&sxp[r * 128 + c0];
        xb[r] = xd.x * wv.x + xd.y * wv.y + xd.z * wv.z + xd.w * wv.w;
    }
#pragma unroll
    for (int o = 16; o; o >>= 1)
#pragma unroll
        for (int j = 0; j < 10; j++)
            xb[j] += __shfl_xor_sync(0xffffffffu, xb[j], o);

    float av[4], bxv[4];
    float xdv[4] = {xd.x, xd.y, xd.z, xd.w};
#pragma unroll
    for (int j = 0; j < 4; j++) {
        int c = c0 + j;
        float4 w0 = *(const float4*)&dtw[c * 8];
        float4 w1 = *(const float4*)&dtw[c * 8 + 4];
        float dtr = __ldg(&dtb[c])
            + w0.x * xb[0] + w0.y * xb[1] + w0.z * xb[2] + w0.w * xb[3]
            + w1.x * xb[4] + w1.y * xb[5] + w1.z * xb[6] + w1.w * xb[7];
        float delta = softplusf(dtr);
        av[j] = __expf(-__expf(__ldg(&alog[c])) * delta);
        bxv[j] = delta * xb[8] * xdv[j];
    }
    size_t base2 = ((size_t)p * 128 + c0) * 2;
    *(float4*)&g_ab[base2]     = make_float4(av[0], bxv[0], av[1], bxv[1]);
    *(float4*)&g_ab[base2 + 4] = make_float4(av[2], bxv[2], av[3], bxv[3]);
    if (lane == 0) g_C[p] = xb[9];
}

// =====================================================================
// K5/K6/K7: chunked streaming scan (interleaved a/bx)
// =====================================================================
__global__ void k_scan1() {
    const int d = threadIdx.x;
    const int chunk = blockIdx.x, b = blockIdx.y;
    float Ar = 1.f, h = 0.f;
    size_t base2 = ((size_t)(b * HW + chunk * CL) * 128 + d) * 2;
#pragma unroll 4
    for (int i = 0; i < CL; i++) {
        float2 ab = *(const float2*)&g_ab[base2 + (size_t)i * 256];
        Ar *= ab.x;
        h = ab.x * h + ab.y;
    }
    const int idx = (b * NCH + chunk) * Cn + d;
    g_As[idx] = Ar;
    g_Bs[idx] = h;
}

__global__ void k_scan2() {
    const int b = blockIdx.x, d = threadIdx.x;
    float h = 0.f;
#pragma unroll 4
    for (int ch = 0; ch < NCH; ch++) {
        const int idx = (b * NCH + ch) * Cn + d;
        g_hin[idx] = h;
        h = g_As[idx] * h + g_Bs[idx];
    }
}

__global__ void k_scan3(const float* __restrict__ Ds) {
    const int d = threadIdx.x;
    const int chunk = blockIdx.x, b = blockIdx.y;
    const float Dd = Ds[d];
    float h = g_hin[(b * NCH + chunk) * Cn + d];
    const int pbase = b * HW + chunk * CL;
    size_t base = (size_t)pbase * Cn + d;
    size_t base2 = base * 2 - (size_t)d;            // == (pbase*128)*2 + d*2
    base2 = ((size_t)pbase * 128 + d) * 2;
#pragma unroll 4
    for (int i = 0; i < CL; i++) {
        float2 ab = *(const float2*)&g_ab[base2 + (size_t)i * 256];
        float xv = g_xd[base + (size_t)i * Cn];
        h = ab.x * h + ab.y;
        g_y[base + (size_t)i * Cn] = h * g_C[pbase + i] + Dd * xv;
    }
}

// =====================================================================
// K8: out_proj GEMM with smem-staged coalesced y load + warp-per-pixel LN
// =====================================================================
__global__ void __launch_bounds__(512) k_out_proj(const float* __restrict__ lng,
                                                  const float* __restrict__ lnb,
                                                  float* __restrict__ out) {
    extern __shared__ char smem[];
    uint32_t sb = smem_to_u32(smem);
    const int t = threadIdx.x, lane = t & 31, warp = t >> 5;
    const int p0 = blockIdx.x * 128, b = p0 >> 14, hw0 = p0 & 16383;

    // phase 1: stage y tile (64KB) into B region, fully coalesced
    float* ys = (float*)(smem + SM_B_HI);
    {
        const float4* src = (const float4*)(g_y + (size_t)p0 * 128);
        float4* dst = (float4*)ys;
        for (int i = t; i < 4096; i += 512) dst[i] = src[i];
    }
    __syncthreads();

    // phase 2: LN per pixel (warp w -> pixels w*8..w*8+7), write bf16 split to A region
    {
        const float4 gv = __ldg((const float4*)lng + lane);
        const float4 bv = __ldg((const float4*)lnb + lane);
#pragma unroll
        for (int j = 0; j < 8; j++) {
            int p = warp * 8 + j;
            float4 v = *(const float4*)&ys[p * 128 + lane * 4];
            float s1 = v.x + v.y + v.z + v.w;
            float s2 = v.x * v.x + v.y * v.y + v.z * v.z + v.w * v.w;
#pragma unroll
            for (int o = 16; o; o >>= 1) {
                s1 += __shfl_xor_sync(0xffffffffu, s1, o);
                s2 += __shfl_xor_sync(0xffffffffu, s2, o);
            }
            float m = s1 * (1.f / 128.f);
            float rs = rsqrtf(s2 * (1.f / 128.f) - m * m + 1e-6f);
            float a0 = (v.x - m) * rs * gv.x + bv.x;
            float a1 = (v.y - m) * rs * gv.y + bv.y;
            float a2 = (v.z - m) * rs * gv.z + bv.z;
            float a3 = (v.w - m) * rs * gv.w + bv.w;
            __nv_bfloat16 h0 = __float2bfloat16(a0), h1 = __float2bfloat16(a1);
            __nv_bfloat16 h2 = __float2bfloat16(a2), h3 = __float2bfloat16(a3);
            __nv_bfloat16 l0 = __float2bfloat16(a0 - __bfloat162float(h0));
            __nv_bfloat16 l1 = __float2bfloat16(a1 - __bfloat162float(h1));
            __nv_bfloat16 l2 = __float2bfloat16(a2 - __bfloat162float(h2));
            __nv_bfloat16 l3 = __float2bfloat16(a3 - __bfloat162float(h3));
            uint32_t off = sw_off(p, lane * 4);
            uint2 hp, lp;
            hp.x = (uint32_t)__bfloat16_as_ushort(h0) | ((uint32_t)__bfloat16_as_ushort(h1) << 16);
            hp.y = (uint32_t)__bfloat16_as_ushort(h2) | ((uint32_t)__bfloat16_as_ushort(h3) << 16);
            lp.x = (uint32_t)__bfloat16_as_ushort(l0) | ((uint32_t)__bfloat16_as_ushort(l1) << 16);
            lp.y = (uint32_t)__bfloat16_as_ushort(l2) | ((uint32_t)__bfloat16_as_ushort(l3) << 16);
            *(uint2*)(smem + SM_A_HI + off) = hp;
            *(uint2*)(smem + SM_A_LO + off) = lp;
        }
    }
    __syncthreads();

    // phase 3: weights into B region (overwrites y staging)
    copy_weights_sw<512>(smem, g_wbhi_out, g_wblo_out, t);
    __syncthreads();

    float acc[8][4];
#pragma unroll
    for (int j = 0; j < 8; j++)
#pragma unroll
        for (int q = 0; q < 4; q++) acc[j][q] = 0.f;

    const int m0 = (warp >> 1) * 16, n0 = (warp & 1) * 64;
    gemm_mma16(sb + SM_A_HI, sb + SM_A_LO, sb + SM_B_HI, sb + SM_B_LO, lane, m0, n0, acc);

    __syncthreads();
    float* stg = (float*)smem;   // [128 outputs][132] pixels
#pragma unroll
    for (int ni = 0; ni < 8; ni++) {
        int row = m0 + (lane >> 2);
        int col = n0 + ni * 8 + (lane & 3) * 2;
        stg[(col)     * 132 + row]     = acc[ni][0];
        stg[(col + 1) * 132 + row]     = acc[ni][1];
        stg[(col)     * 132 + row + 8] = acc[ni][2];
        stg[(col + 1) * 132 + row + 8] = acc[ni][3];
    }
    __syncthreads();
    for (int i = t; i < 4096; i += 512) {
        int o = i >> 5, m4 = i & 31;
        float4 v4 = *(const float4*)&stg[o * 132 + m4 * 4];
        *(float4*)&out[(size_t)(b * 128 + o) * HW + hw0 + m4 * 4] = v4;
    }
}

// =====================================================================
extern "C" void kernel_launch(void* const* d_in, const int* in_sizes, int n_in,
                              void* d_out, int out_size) {
    const float* x      = (const float*)d_in[0];
    const float* inw    = (const float*)d_in[1];
    const float* c2w    = (const float*)d_in[2];
    const float* c2b    = (const float*)d_in[3];
    const float* dww    = (const float*)d_in[4];
    const float* dwb    = (const float*)d_in[5];
    const float* dlng   = (const float*)d_in[6];
    const float* dlnb   = (const float*)d_in[7];
    const float* offw   = (const float*)d_in[8];
    const float* offb   = (const float*)d_in[9];
    const float* xpw    = (const float*)d_in[10];
    const float* dtw    = (const float*)d_in[11];
    const float* dtb    = (const float*)d_in[12];
    const float* alog   = (const float*)d_in[13];
    const float* Ds     = (const float*)d_in[14];
    const float* olng   = (const float*)d_in[15];
    const float* olnb   = (const float*)d_in[16];
    const float* outw   = (const float*)d_in[17];
    float* out = (float*)d_out;

    cudaFuncSetAttribute(k_in_proj,  cudaFuncAttributeMaxDynamicSharedMemorySize, SM_GEMM);
    cudaFuncSetAttribute(k_out_proj, cudaFuncAttributeMaxDynamicSharedMemorySize, SM_GEMM);

    k_prep_w<<<128, 256>>>(inw, outw);              // 1
    k_in_proj<<<P / 128, 512, SM_GEMM>>>(x);        // 2
    k_dwsilu<<<P / 32, 256>>>(c2w, c2b);            // 3
    k_dw2_off<<<P / 32, 256>>>(dww, dwb, dlng, dlnb, offw, offb);  // 4  <- ncu slot
    k_dcn_delta<<<P / 8, 256>>>(xpw, dtw, dtb, alog);              // 5
    k_scan1<<<dim3(NCH, Bz), 128>>>();              // 6
    k_scan2<<<Bz, 128>>>();                         // 7
    k_scan3<<<dim3(NCH, Bz), 128>>>(Ds);            // 8
    k_out_proj<<<P / 128, 512, SM_GEMM>>>(olng, olnb, out);        // 9
}

// round 10
// speedup vs baseline: 1.3819x; 1.3819x over previous
#include <cuda_runtime.h>
#include <cuda_bf16.h>
#include <cstdint>

// ---------------- problem constants ----------------
constexpr int Bz = 4, Cn = 128, Hh = 128, Wd = 128;
constexpr int HW = Hh * Wd;       // 16384
constexpr int P  = Bz * HW;       // 65536 pixels
constexpr int NCH = 256, CL = 64; // scan: 256 chunks of 64 steps

// ---------------- scratch ----------------
__device__ float g_xin [P * Cn];
__device__ float g_xc  [P * Cn];
__device__ float g_off [P * 16];
__device__ float g_xd  [P * Cn];
__device__ float g_a   [P * Cn];
__device__ float g_bx  [P * Cn];
__device__ float g_C   [P];
__device__ float g_y   [P * Cn];
__device__ float g_As  [Bz * NCH * Cn];
__device__ float g_Bs  [Bz * NCH * Cn];
__device__ float g_hin [Bz * NCH * Cn];
// bf16 hi/lo weight images, row-major [o][c]
__device__ __align__(16) unsigned short g_wbhi_in [16384];
__device__ __align__(16) unsigned short g_wblo_in [16384];
__device__ __align__(16) unsigned short g_wbhi_out[16384];
__device__ __align__(16) unsigned short g_wblo_out[16384];

__device__ __forceinline__ uint32_t smem_to_u32(const void* p) {
    uint32_t a;
    asm("{ .reg .u64 t; cvta.to.shared.u64 t, %1; cvt.u32.u64 %0, t; }" : "=r"(a) : "l"(p));
    return a;
}

// smem tile layout: row stride 256B (128 bf16), 16B chunks XOR-swizzled by row
__device__ __forceinline__ uint32_t sw_off(int row, int k) {
    int chunk = k >> 3;
    int swch = (chunk & 8) | ((chunk ^ row) & 7);
    return (uint32_t)(row * 256 + swch * 16 + (k & 7) * 2);
}

#define LDSM_X4(r0, r1, r2, r3, addr) \
    asm volatile("ldmatrix.sync.aligned.m8n8.x4.shared.b16 {%0,%1,%2,%3}, [%4];" \
                 : "=r"(r0), "=r"(r1), "=r"(r2), "=r"(r3) : "r"(addr))
#define MMA16816(d, a, b0v, b1v) \
    asm volatile("mma.sync.aligned.m16n8k16.row.col.f32.bf16.bf16.f32 " \
                 "{%0,%1,%2,%3}, {%4,%5,%6,%7}, {%8,%9}, {%0,%1,%2,%3};" \
                 : "+f"((d)[0]), "+f"((d)[1]), "+f"((d)[2]), "+f"((d)[3]) \
                 : "r"((a)[0]), "r"((a)[1]), "r"((a)[2]), "r"((a)[3]), "r"(b0v), "r"(b1v))

// dyn smem layout for GEMM kernels (128KB)
constexpr int SM_A_HI = 0, SM_A_LO = 32768, SM_B_HI = 65536, SM_B_LO = 98304;
constexpr int SM_GEMM = 131072;

// =====================================================================
// K0: split weights into bf16 hi/lo (row-major [o][c])
// =====================================================================
__global__ void k_prep_w(const float* __restrict__ inw, const float* __restrict__ outw) {
    int idx = blockIdx.x * 256 + threadIdx.x;   // 32768 total
    int which = idx >> 14, rem = idx & 16383;
    float v = (which ? outw : inw)[rem];
    __nv_bfloat16 h = __float2bfloat16(v);
    __nv_bfloat16 l = __float2bfloat16(v - __bfloat162float(h));
    if (which) { g_wbhi_out[rem] = __bfloat16_as_ushort(h); g_wblo_out[rem] = __bfloat16_as_ushort(l); }
    else       { g_wbhi_in [rem] = __bfloat16_as_ushort(h); g_wblo_in [rem] = __bfloat16_as_ushort(l); }
}

// =====================================================================
// core mma loop: warp tile 16M x 64N, K=128, 3-term hi/lo bf16
// =====================================================================
__device__ __forceinline__ void gemm_mma16(uint32_t sAhi, uint32_t sAlo,
                                           uint32_t sBhi, uint32_t sBlo,
                                           int lane, int m0, int n0,
                                           float acc[8][4]) {
    const int aRow = lane & 15;
    const int aK   = (lane >> 4) << 3;
    const int bRow = (lane & 7) | (((lane >> 4) & 1) << 3);
    const int bK   = ((lane >> 3) & 1) << 3;
#pragma unroll
    for (int kk = 0; kk < 128; kk += 16) {
        uint32_t ah[4], al[4], bh[4][4], bl[4][4];
        {
            uint32_t off = sw_off(m0 + aRow, kk + aK);
            LDSM_X4(ah[0], ah[1], ah[2], ah[3], sAhi + off);
            LDSM_X4(al[0], al[1], al[2], al[3], sAlo + off);
        }
#pragma unroll
        for (int nq = 0; nq < 4; nq++) {
            uint32_t off = sw_off(n0 + nq * 16 + bRow, kk + bK);
            LDSM_X4(bh[nq][0], bh[nq][1], bh[nq][2], bh[nq][3], sBhi + off);
            LDSM_X4(bl[nq][0], bl[nq][1], bl[nq][2], bl[nq][3], sBlo + off);
        }
#pragma unroll
        for (int nq = 0; nq < 4; nq++)
#pragma unroll
            for (int hf = 0; hf < 2; hf++) {
                float* d = acc[nq * 2 + hf];
                MMA16816(d, ah, bh[nq][hf * 2], bh[nq][hf * 2 + 1]);
                MMA16816(d, al, bh[nq][hf * 2], bh[nq][hf * 2 + 1]);
                MMA16816(d, ah, bl[nq][hf * 2], bl[nq][hf * 2 + 1]);
            }
    }
}

template<int NT>
__device__ __forceinline__ void copy_weights_sw(char* smem, const unsigned short* ghi,
                                                const unsigned short* glo, int t) {
    const uint4* shi = (const uint4*)ghi;
    const uint4* slo = (const uint4*)glo;
#pragma unroll
    for (int i = t; i < 2048; i += NT) {
        int row = i >> 4, chunk = i & 15;
        uint32_t doff = row * 256 + ((((chunk ^ row) & 7) | (chunk & 8)) << 4);
        *(uint4*)(smem + SM_B_HI + doff) = shi[i];
        *(uint4*)(smem + SM_B_LO + doff) = slo[i];
    }
}

// =====================================================================
// K1: in_proj GEMM.  x (B,C,HW) -> xin channels-last (p,c)
// =====================================================================
__global__ void __launch_bounds__(512) k_in_proj(const float* __restrict__ x) {
    extern __shared__ char smem[];
    uint32_t sb = smem_to_u32(smem);
    const int t = threadIdx.x, lane = t & 31, warp = t >> 5;
    const int p0 = blockIdx.x * 128, b = p0 >> 14, hw0 = p0 & 16383;

    copy_weights_sw<512>(smem, g_wbhi_in, g_wblo_in, t);
    for (int i = t; i < 16384; i += 512) {
        int c = i >> 7, m = i & 127;
        float v = x[(size_t)(b * 128 + c) * HW + hw0 + m];
        __nv_bfloat16 h = __float2bfloat16(v);
        __nv_bfloat16 l = __float2bfloat16(v - __bfloat162float(h));
        uint32_t off = sw_off(m, c);
        *(unsigned short*)(smem + SM_A_HI + off) = __bfloat16_as_ushort(h);
        *(unsigned short*)(smem + SM_A_LO + off) = __bfloat16_as_ushort(l);
    }
    __syncthreads();

    float acc[8][4];
#pragma unroll
    for (int j = 0; j < 8; j++)
#pragma unroll
        for (int q = 0; q < 4; q++) acc[j][q] = 0.f;

    const int m0 = (warp >> 1) * 16, n0 = (warp & 1) * 64;
    gemm_mma16(sb + SM_A_HI, sb + SM_A_LO, sb + SM_B_HI, sb + SM_B_LO, lane, m0, n0, acc);

#pragma unroll
    for (int ni = 0; ni < 8; ni++) {
        int row = m0 + (lane >> 2);
        int col = n0 + ni * 8 + (lane & 3) * 2;
        *(float2*)&g_xin[(size_t)(p0 + row) * 128 + col] =
            make_float2(acc[ni][0], acc[ni][1]);
        *(float2*)&g_xin[(size_t)(p0 + row + 8) * 128 + col] =
            make_float2(acc[ni][2], acc[ni][3]);
    }
}

// =====================================================================
// K2: depthwise 3x3 conv + bias + SiLU. WARP = 4 consecutive pixels.
// =====================================================================
__global__ void __launch_bounds__(256) k_dwsilu(const float* __restrict__ w,
                                                const float* __restrict__ bias) {
    __shared__ float sw[9 * 128];
    __shared__ float sb2[128];
    const int t = threadIdx.x;
    for (int i = t; i < 1152; i += 256) {
        int c = i / 9, k = i - c * 9;
        sw[k * 128 + c] = w[i];
    }
    if (t < 128) sb2[t] = bias[t];
    __syncthreads();

    const int warp = t >> 5, lane = t & 31, c0 = lane * 4;
    const int p0 = blockIdx.x * 32 + warp * 4;
    const int b = p0 >> 14, hw = p0 & 16383, yy = hw >> 7, xx0 = hw & 127;

    float4 bv = *(const float4*)&sb2[c0];
    float4 acc[4] = {bv, bv, bv, bv};
#pragma unroll
    for (int ky = 0; ky < 3; ky++) {
        int yv = yy + ky - 1;
        if ((unsigned)yv >= (unsigned)Hh) continue;
        const float* rowb = &g_xin[(size_t)(b * HW + yv * Wd) * Cn + c0];
        float4 v[6];
#pragma unroll
        for (int col = 0; col < 6; col++) {
            int xv = xx0 - 1 + col;
            v[col] = ((unsigned)xv < (unsigned)Wd) ? *(const float4*)&rowb[(size_t)xv * Cn]
                                                   : make_float4(0.f, 0.f, 0.f, 0.f);
        }
        float4 wv[3];
#pragma unroll
        for (int kx = 0; kx < 3; kx++) wv[kx] = *(const float4*)&sw[(ky * 3 + kx) * 128 + c0];
#pragma unroll
        for (int j = 0; j < 4; j++)
#pragma unroll
            for (int kx = 0; kx < 3; kx++) {
                float4 vv = v[j + kx];
                acc[j].x += wv[kx].x * vv.x; acc[j].y += wv[kx].y * vv.y;
                acc[j].z += wv[kx].z * vv.z; acc[j].w += wv[kx].w * vv.w;
            }
    }
#pragma unroll
    for (int j = 0; j < 4; j++) {
        float4 r;
        r.x = acc[j].x / (1.f + __expf(-acc[j].x));
        r.y = acc[j].y / (1.f + __expf(-acc[j].y));
        r.z = acc[j].z / (1.f + __expf(-acc[j].z));
        r.w = acc[j].w / (1.f + __expf(-acc[j].w));
        *(float4*)&g_xc[(size_t)(p0 + j) * Cn + c0] = r;
    }
}

__device__ __forceinline__ float softplusf(float x) {
    return fmaxf(x, 0.f) + log1pf(__expf(-fabsf(x)));
}

// =====================================================================
// K3: dwconv(dw_w) -> LN -> GELU -> offsets.  WARP = 2 pixels (reg relief).
// 256 threads = 8 warps = 16 pixels/block.
// =====================================================================
__global__ void __launch_bounds__(256) k_dw2_off(const float* __restrict__ w,
                          const float* __restrict__ bias,
                          const float* __restrict__ lng, const float* __restrict__ lnb,
                          const float* __restrict__ offw, const float* __restrict__ offb) {
    __shared__ float sw[9 * 128];
    __shared__ float sb[128], sg[128], sbt[128];
    __shared__ float sofw[16 * 128];
    __shared__ float sofb[16];
    const int t = threadIdx.x;
    for (int i = t; i < 1152; i += 256) {
        int c = i / 9, k = i - c * 9;
        sw[k * 128 + c] = w[i];
    }
    for (int i = t; i < 2048; i += 256) sofw[i] = offw[i];
    if (t < 128) { sb[t] = bias[t]; sg[t] = lng[t]; sbt[t] = lnb[t]; }
    if (t < 16) sofb[t] = offb[t];
    __syncthreads();

    const int warp = t >> 5, lane = t & 31, c0 = lane * 4;
    const int p0 = blockIdx.x * 16 + warp * 2;
    const int b = p0 >> 14, hw = p0 & 16383, yy = hw >> 7, xx0 = hw & 127;

    // dwconv + bias, 2 pixels with horizontal tap reuse (4 cols)
    float4 bv = *(const float4*)&sb[c0];
    float4 acc[2] = {bv, bv};
#pragma unroll
    for (int ky = 0; ky < 3; ky++) {
        int yv = yy + ky - 1;
        if ((unsigned)yv >= (unsigned)Hh) continue;
        const float* rowb = &g_xc[(size_t)(b * HW + yv * Wd) * Cn + c0];
        float4 v[4];
#pragma unroll
        for (int col = 0; col < 4; col++) {
            int xv = xx0 - 1 + col;
            v[col] = ((unsigned)xv < (unsigned)Wd) ? *(const float4*)&rowb[(size_t)xv * Cn]
                                                   : make_float4(0.f, 0.f, 0.f, 0.f);
        }
        float4 wv[3];
#pragma unroll
        for (int kx = 0; kx < 3; kx++) wv[kx] = *(const float4*)&sw[(ky * 3 + kx) * 128 + c0];
#pragma unroll
        for (int j = 0; j < 2; j++)
#pragma unroll
            for (int kx = 0; kx < 3; kx++) {
                float4 vv = v[j + kx];
                acc[j].x += wv[kx].x * vv.x; acc[j].y += wv[kx].y * vv.y;
                acc[j].z += wv[kx].z * vv.z; acc[j].w += wv[kx].w * vv.w;
            }
    }

    const float4 gl = *(const float4*)&sg[c0];
    const float4 bl = *(const float4*)&sbt[c0];
#pragma unroll
    for (int j = 0; j < 2; j++) {
        float s1 = acc[j].x + acc[j].y + acc[j].z + acc[j].w;
        float s2 = acc[j].x * acc[j].x + acc[j].y * acc[j].y
                 + acc[j].z * acc[j].z + acc[j].w * acc[j].w;
#pragma unroll
        for (int o = 16; o; o >>= 1) {
            s1 += __shfl_xor_sync(0xffffffffu, s1, o);
            s2 += __shfl_xor_sync(0xffffffffu, s2, o);
        }
        const float m = s1 * (1.f / 128.f);
        const float rs = rsqrtf(s2 * (1.f / 128.f) - m * m + 1e-6f);
        float xn0 = (acc[j].x - m) * rs * gl.x + bl.x;
        float xn1 = (acc[j].y - m) * rs * gl.y + bl.y;
        float xn2 = (acc[j].z - m) * rs * gl.z + bl.z;
        float xn3 = (acc[j].w - m) * rs * gl.w + bl.w;
        float u0 = 0.5f * xn0 * (1.f + erff(xn0 * 0.70710678118654752f));
        float u1 = 0.5f * xn1 * (1.f + erff(xn1 * 0.70710678118654752f));
        float u2 = 0.5f * xn2 * (1.f + erff(xn2 * 0.70710678118654752f));
        float u3 = 0.5f * xn3 * (1.f + erff(xn3 * 0.70710678118654752f));

        float oacc[16];
#pragma unroll
        for (int o = 0; o < 16; o++) {
            float4 wv = *(const float4*)&sofw[o * 128 + c0];
            oacc[o] = u0 * wv.x + u1 * wv.y + u2 * wv.z + u3 * wv.w;
        }
#pragma unroll
        for (int o = 16; o; o >>= 1)
#pragma unroll
            for (int q = 0; q < 16; q++)
                oacc[q] += __shfl_xor_sync(0xffffffffu, oacc[q], o);
        if (lane < 16) g_off[(p0 + j) * 16 + lane] = oacc[lane] + sofb[lane];
    }
}

// =====================================================================
// K4: DCNv3 sample + x_dbl + delta precompute.  WARP PER PIXEL.
// =====================================================================
__global__ void __launch_bounds__(256) k_dcn_delta(const float* __restrict__ xpw,
                            const float* __restrict__ dtw, const float* __restrict__ dtb,
                            const float* __restrict__ alog) {
    __shared__ float sxp[10 * 128];
    const int t = threadIdx.x;
    for (int i = t; i < 1280; i += 256) sxp[i] = xpw[i];
    __syncthreads();

    const int p = blockIdx.x * 8 + (t >> 5);
    const int lane = t & 31, c0 = lane * 4;
    const int b = p >> 14, hw = p & 16383, yy = hw >> 7, xx = hw & 127;
    const int g = lane >> 2;

    const float ox = g_off[p * 16 + 2 * g];
    const float oy = g_off[p * 16 + 2 * g + 1];
    const float px = (float)xx + ox, py = (float)yy + oy;
    const float x0 = floorf(px), y0 = floorf(py);
    const float wx = px - x0, wy = py - y0;
    float4 xd = make_float4(0.f, 0.f, 0.f, 0.f);
#pragma unroll
    for (int dy = 0; dy < 2; dy++) {
#pragma unroll
        for (int dx = 0; dx < 2; dx++) {
            float yif = y0 + (float)dy, xif = x0 + (float)dx;
            float wgt = (dy ? wy : 1.f - wy) * (dx ? wx : 1.f - wx);
            bool valid = (yif >= 0.f) && (yif < (float)Hh) && (xif >= 0.f) && (xif < (float)Wd);
            wgt = valid ? wgt : 0.f;
            int yi = (int)fminf(fmaxf(yif, 0.f), (float)(Hh - 1));
            int xi = (int)fminf(fmaxf(xif, 0.f), (float)(Wd - 1));
            float4 v = *(const float4*)&g_xc[(size_t)(b * HW + yi * Wd + xi) * Cn + c0];
            xd.x += v.x * wgt; xd.y += v.y * wgt; xd.z += v.z * wgt; xd.w += v.w * wgt;
        }
    }
    *(float4*)&g_xd[(size_t)p * Cn + c0] = xd;

    float xb[10];
#pragma unroll
    for (int r = 0; r < 10; r++) {
        float4 wv = *(const float4*)&sxp[r * 128 + c0];
        xb[r] = xd.x * wv.x + xd.y * wv.y + xd.z * wv.z + xd.w * wv.w;
    }
#pragma unroll
    for (int o = 16; o; o >>= 1)
#pragma unroll
        for (int j = 0; j < 10; j++)
            xb[j] += __shfl_xor_sync(0xffffffffu, xb[j], o);

    float av[4], bxv[4];
    float xdv[4] = {xd.x, xd.y, xd.z, xd.w};
#pragma unroll
    for (int j = 0; j < 4; j++) {
        int c = c0 + j;
        float4 w0 = *(const float4*)&dtw[c * 8];
        float4 w1 = *(const float4*)&dtw[c * 8 + 4];
        float dtr = __ldg(&dtb[c])
            + w0.x * xb[0] + w0.y * xb[1] + w0.z * xb[2] + w0.w * xb[3]
            + w1.x * xb[4] + w1.y * xb[5] + w1.z * xb[6] + w1.w * xb[7];
        float delta = softplusf(dtr);
        av[j] = __expf(-__expf(__ldg(&alog[c])) * delta);
        bxv[j] = delta * xb[8] * xdv[j];
    }
    *(float4*)&g_a [(size_t)p * Cn + c0] = make_float4(av[0], av[1], av[2], av[3]);
    *(float4*)&g_bx[(size_t)p * Cn + c0] = make_float4(bxv[0], bxv[1], bxv[2], bxv[3]);
    if (lane == 0) g_C[p] = xb[9];
}

// =====================================================================
// K5/K6/K7: chunked streaming scan
// =====================================================================
__global__ void k_scan1() {
    const int d = threadIdx.x;
    const int chunk = blockIdx.x, b = blockIdx.y;
    float Ar = 1.f, h = 0.f;
    size_t base = ((size_t)(b * HW + chunk * CL)) * Cn + d;
#pragma unroll 4
    for (int i = 0; i < CL; i++) {
        float a  = g_a [base + (size_t)i * Cn];
        float bx = g_bx[base + (size_t)i * Cn];
        Ar *= a;
        h = a * h + bx;
    }
    const int idx = (b * NCH + chunk) * Cn + d;
    g_As[idx] = Ar;
    g_Bs[idx] = h;
}

__global__ void k_scan2() {
    const int b = blockIdx.x, d = threadIdx.x;
    float h = 0.f;
#pragma unroll 4
    for (int ch = 0; ch < NCH; ch++) {
        const int idx = (b * NCH + ch) * Cn + d;
        g_hin[idx] = h;
        h = g_As[idx] * h + g_Bs[idx];
    }
}

__global__ void k_scan3(const float* __restrict__ Ds) {
    const int d = threadIdx.x;
    const int chunk = blockIdx.x, b = blockIdx.y;
    const float Dd = Ds[d];
    float h = g_hin[(b * NCH + chunk) * Cn + d];
    const int pbase = b * HW + chunk * CL;
    size_t base = (size_t)pbase * Cn + d;
#pragma unroll 4
    for (int i = 0; i < CL; i++) {
        float a  = g_a [base + (size_t)i * Cn];
        float bx = g_bx[base + (size_t)i * Cn];
        float xv = g_xd[base + (size_t)i * Cn];
        h = a * h + bx;
        g_y[base + (size_t)i * Cn] = h * g_C[pbase + i] + Dd * xv;
    }
}

// =====================================================================
// K8: out_proj GEMM. Warp-per-pixel LN directly from gmem (coalesced),
// writing bf16 hi/lo split into the swizzled A region. Rest as R8.
// =====================================================================
__global__ void __launch_bounds__(512) k_out_proj(const float* __restrict__ lng,
                                                  const float* __restrict__ lnb,
                                                  float* __restrict__ out) {
    extern __shared__ char smem[];
    uint32_t sb = smem_to_u32(smem);
    const int t = threadIdx.x, lane = t & 31, warp = t >> 5;
    const int p0 = blockIdx.x * 128, b = p0 >> 14, hw0 = p0 & 16383;

    copy_weights_sw<512>(smem, g_wbhi_out, g_wblo_out, t);

    // warp-per-pixel LN: warp w handles pixels w*8 .. w*8+7 (one coalesced
    // float4 row read per pixel), butterfly stats, split to smem A.
    {
        const float4 gv = __ldg((const float4*)lng + lane);
        const float4 bv = __ldg((const float4*)lnb + lane);
#pragma unroll
        for (int j = 0; j < 8; j++) {
            int p = warp * 8 + j;
            float4 v = *(const float4*)&g_y[(size_t)(p0 + p) * 128 + lane * 4];
            float s1 = v.x + v.y + v.z + v.w;
            float s2 = v.x * v.x + v.y * v.y + v.z * v.z + v.w * v.w;
#pragma unroll
            for (int o = 16; o; o >>= 1) {
                s1 += __shfl_xor_sync(0xffffffffu, s1, o);
                s2 += __shfl_xor_sync(0xffffffffu, s2, o);
            }
            float m = s1 * (1.f / 128.f);
            float rs = rsqrtf(s2 * (1.f / 128.f) - m * m + 1e-6f);
            float a0 = (v.x - m) * rs * gv.x + bv.x;
            float a1 = (v.y - m) * rs * gv.y + bv.y;
            float a2 = (v.z - m) * rs * gv.z + bv.z;
            float a3 = (v.w - m) * rs * gv.w + bv.w;
            __nv_bfloat16 h0 = __float2bfloat16(a0), h1 = __float2bfloat16(a1);
            __nv_bfloat16 h2 = __float2bfloat16(a2), h3 = __float2bfloat16(a3);
            __nv_bfloat16 l0 = __float2bfloat16(a0 - __bfloat162float(h0));
            __nv_bfloat16 l1 = __float2bfloat16(a1 - __bfloat162float(h1));
            __nv_bfloat16 l2 = __float2bfloat16(a2 - __bfloat162float(h2));
            __nv_bfloat16 l3 = __float2bfloat16(a3 - __bfloat162float(h3));
            uint32_t off = sw_off(p, lane * 4);
            uint2 hp, lp;
            hp.x = (uint32_t)__bfloat16_as_ushort(h0) | ((uint32_t)__bfloat16_as_ushort(h1) << 16);
            hp.y = (uint32_t)__bfloat16_as_ushort(h2) | ((uint32_t)__bfloat16_as_ushort(h3) << 16);
            lp.x = (uint32_t)__bfloat16_as_ushort(l0) | ((uint32_t)__bfloat16_as_ushort(l1) << 16);
            lp.y = (uint32_t)__bfloat16_as_ushort(l2) | ((uint32_t)__bfloat16_as_ushort(l3) << 16);
            *(uint2*)(smem + SM_A_HI + off) = hp;
            *(uint2*)(smem + SM_A_LO + off) = lp;
        }
    }
    __syncthreads();

    float acc[8][4];
#pragma unroll
    for (int j = 0; j < 8; j++)
#pragma unroll
        for (int q = 0; q < 4; q++) acc[j][q] = 0.f;

    const int m0 = (warp >> 1) * 16, n0 = (warp & 1) * 64;
    gemm_mma16(sb + SM_A_HI, sb + SM_A_LO, sb + SM_B_HI, sb + SM_B_LO, lane, m0, n0, acc);

    __syncthreads();
    float* stg = (float*)smem;   // [128 outputs][132] pixels
#pragma unroll
    for (int ni = 0; ni < 8; ni++) {
        int row = m0 + (lane >> 2);
        int col = n0 + ni * 8 + (lane & 3) * 2;
        stg[(col)     * 132 + row]     = acc[ni][0];
        stg[(col + 1) * 132 + row]     = acc[ni][1];
        stg[(col)     * 132 + row + 8] = acc[ni][2];
        stg[(col + 1) * 132 + row + 8] = acc[ni][3];
    }
    __syncthreads();
    for (int i = t; i < 4096; i += 512) {
        int o = i >> 5, m4 = i & 31;
        float4 v4 = *(const float4*)&stg[o * 132 + m4 * 4];
        *(float4*)&out[(size_t)(b * 128 + o) * HW + hw0 + m4 * 4] = v4;
    }
}

// =====================================================================
extern "C" void kernel_launch(void* const* d_in, const int* in_sizes, int n_in,
                              void* d_out, int out_size) {
    const float* x      = (const float*)d_in[0];
    const float* inw    = (const float*)d_in[1];
    const float* c2w    = (const float*)d_in[2];
    const float* c2b    = (const float*)d_in[3];
    const float* dww    = (const float*)d_in[4];
    const float* dwb    = (const float*)d_in[5];
    const float* dlng   = (const float*)d_in[6];
    const float* dlnb   = (const float*)d_in[7];
    const float* offw   = (const float*)d_in[8];
    const float* offb   = (const float*)d_in[9];
    const float* xpw    = (const float*)d_in[10];
    const float* dtw    = (const float*)d_in[11];
    const float* dtb    = (const float*)d_in[12];
    const float* alog   = (const float*)d_in[13];
    const float* Ds     = (const float*)d_in[14];
    const float* olng   = (const float*)d_in[15];
    const float* olnb   = (const float*)d_in[16];
    const float* outw   = (const float*)d_in[17];
    float* out = (float*)d_out;

    cudaFuncSetAttribute(k_in_proj,  cudaFuncAttributeMaxDynamicSharedMemorySize, SM_GEMM);
    cudaFuncSetAttribute(k_out_proj, cudaFuncAttributeMaxDynamicSharedMemorySize, SM_GEMM);

    k_prep_w<<<128, 256>>>(inw, outw);              // 1
    k_in_proj<<<P / 128, 512, SM_GEMM>>>(x);        // 2
    k_dwsilu<<<P / 32, 256>>>(c2w, c2b);            // 3
    k_dw2_off<<<P / 16, 256>>>(dww, dwb, dlng, dlnb, offw, offb);  // 4  <- ncu slot
    k_dcn_delta<<<P / 8, 256>>>(xpw, dtw, dtb, alog);              // 5
    k_scan1<<<dim3(NCH, Bz), 128>>>();              // 6
    k_scan2<<<Bz, 128>>>();                         // 7
    k_scan3<<<dim3(NCH, Bz), 128>>>(Ds);            // 8
    k_out_proj<<<P / 128, 512, SM_GEMM>>>(olng, olnb, out);        // 9
}

// round 11
// speedup vs baseline: 1.4482x; 1.0479x over previous
#include <cuda_runtime.h>
#include <cuda_bf16.h>
#include <cstdint>

// ---------------- problem constants ----------------
constexpr int Bz = 4, Cn = 128, Hh = 128, Wd = 128;
constexpr int HW = Hh * Wd;       // 16384
constexpr int P  = Bz * HW;       // 65536 pixels
constexpr int NCH = 256, CL = 64; // scan: 256 chunks of 64 steps

// ---------------- scratch ----------------
__device__ float g_xin [P * Cn];
__device__ float g_xc  [P * Cn];
__device__ float g_off [P * 16];
__device__ float g_xd  [P * Cn];
__device__ float g_a   [P * Cn];
__device__ float g_bx  [P * Cn];
__device__ float g_C   [P];
__device__ float g_y   [P * Cn];
__device__ float g_As  [Bz * NCH * Cn];
__device__ float g_Bs  [Bz * NCH * Cn];
__device__ float g_hin [Bz * NCH * Cn];
// bf16 hi/lo weight images, row-major [o][c]
__device__ __align__(16) unsigned short g_wbhi_in [16384];
__device__ __align__(16) unsigned short g_wblo_in [16384];
__device__ __align__(16) unsigned short g_wbhi_out[16384];
__device__ __align__(16) unsigned short g_wblo_out[16384];

__device__ __forceinline__ uint32_t smem_to_u32(const void* p) {
    uint32_t a;
    asm("{ .reg .u64 t; cvta.to.shared.u64 t, %1; cvt.u32.u64 %0, t; }" : "=r"(a) : "l"(p));
    return a;
}

// smem tile layout: row stride 256B (128 bf16), 16B chunks XOR-swizzled by row
__device__ __forceinline__ uint32_t sw_off(int row, int k) {
    int chunk = k >> 3;
    int swch = (chunk & 8) | ((chunk ^ row) & 7);
    return (uint32_t)(row * 256 + swch * 16 + (k & 7) * 2);
}

#define LDSM_X4(r0, r1, r2, r3, addr) \
    asm volatile("ldmatrix.sync.aligned.m8n8.x4.shared.b16 {%0,%1,%2,%3}, [%4];" \
                 : "=r"(r0), "=r"(r1), "=r"(r2), "=r"(r3) : "r"(addr))
#define MMA16816(d, a, b0v, b1v) \
    asm volatile("mma.sync.aligned.m16n8k16.row.col.f32.bf16.bf16.f32 " \
                 "{%0,%1,%2,%3}, {%4,%5,%6,%7}, {%8,%9}, {%0,%1,%2,%3};" \
                 : "+f"((d)[0]), "+f"((d)[1]), "+f"((d)[2]), "+f"((d)[3]) \
                 : "r"((a)[0]), "r"((a)[1]), "r"((a)[2]), "r"((a)[3]), "r"(b0v), "r"(b1v))

// dyn smem layout for GEMM kernels (128KB)
constexpr int SM_A_HI = 0, SM_A_LO = 32768, SM_B_HI = 65536, SM_B_LO = 98304;
constexpr int SM_GEMM = 131072;

// =====================================================================
// K0a/K0b: split weights into bf16 hi/lo (row-major [o][c])
// =====================================================================
__global__ void k_prep_in(const float* __restrict__ inw) {
    int rem = blockIdx.x * 256 + threadIdx.x;   // 16384
    float v = inw[rem];
    __nv_bfloat16 h = __float2bfloat16(v);
    __nv_bfloat16 l = __float2bfloat16(v - __bfloat162float(h));
    g_wbhi_in[rem] = __bfloat16_as_ushort(h);
    g_wblo_in[rem] = __bfloat16_as_ushort(l);
}
__global__ void k_prep_out(const float* __restrict__ outw) {
    int rem = blockIdx.x * 256 + threadIdx.x;   // 16384
    float v = outw[rem];
    __nv_bfloat16 h = __float2bfloat16(v);
    __nv_bfloat16 l = __float2bfloat16(v - __bfloat162float(h));
    g_wbhi_out[rem] = __bfloat16_as_ushort(h);
    g_wblo_out[rem] = __bfloat16_as_ushort(l);
}

// =====================================================================
// core mma loop: warp tile 16M x 64N, K=128, 3-term hi/lo bf16
// =====================================================================
__device__ __forceinline__ void gemm_mma16(uint32_t sAhi, uint32_t sAlo,
                                           uint32_t sBhi, uint32_t sBlo,
                                           int lane, int m0, int n0,
                                           float acc[8][4]) {
    const int aRow = lane & 15;
    const int aK   = (lane >> 4) << 3;
    const int bRow = (lane & 7) | (((lane >> 4) & 1) << 3);
    const int bK   = ((lane >> 3) & 1) << 3;
#pragma unroll
    for (int kk = 0; kk < 128; kk += 16) {
        uint32_t ah[4], al[4], bh[4][4], bl[4][4];
        {
            uint32_t off = sw_off(m0 + aRow, kk + aK);
            LDSM_X4(ah[0], ah[1], ah[2], ah[3], sAhi + off);
            LDSM_X4(al[0], al[1], al[2], al[3], sAlo + off);
        }
#pragma unroll
        for (int nq = 0; nq < 4; nq++) {
            uint32_t off = sw_off(n0 + nq * 16 + bRow, kk + bK);
            LDSM_X4(bh[nq][0], bh[nq][1], bh[nq][2], bh[nq][3], sBhi + off);
            LDSM_X4(bl[nq][0], bl[nq][1], bl[nq][2], bl[nq][3], sBlo + off);
        }
#pragma unroll
        for (int nq = 0; nq < 4; nq++)
#pragma unroll
            for (int hf = 0; hf < 2; hf++) {
                float* d = acc[nq * 2 + hf];
                MMA16816(d, ah, bh[nq][hf * 2], bh[nq][hf * 2 + 1]);
                MMA16816(d, al, bh[nq][hf * 2], bh[nq][hf * 2 + 1]);
                MMA16816(d, ah, bl[nq][hf * 2], bl[nq][hf * 2 + 1]);
            }
    }
}

template<int NT>
__device__ __forceinline__ void copy_weights_sw(char* smem, const unsigned short* ghi,
                                                const unsigned short* glo, int t) {
    const uint4* shi = (const uint4*)ghi;
    const uint4* slo = (const uint4*)glo;
#pragma unroll
    for (int i = t; i < 2048; i += NT) {
        int row = i >> 4, chunk = i & 15;
        uint32_t doff = row * 256 + ((((chunk ^ row) & 7) | (chunk & 8)) << 4);
        *(uint4*)(smem + SM_B_HI + doff) = shi[i];
        *(uint4*)(smem + SM_B_LO + doff) = slo[i];
    }
}

// =====================================================================
// K1: in_proj GEMM.  x (B,C,HW) -> xin channels-last (p,c)
// =====================================================================
__global__ void __launch_bounds__(512) k_in_proj(const float* __restrict__ x) {
    extern __shared__ char smem[];
    uint32_t sb = smem_to_u32(smem);
    const int t = threadIdx.x, lane = t & 31, warp = t >> 5;
    const int p0 = blockIdx.x * 128, b = p0 >> 14, hw0 = p0 & 16383;

    copy_weights_sw<512>(smem, g_wbhi_in, g_wblo_in, t);
    for (int i = t; i < 16384; i += 512) {
        int c = i >> 7, m = i & 127;
        float v = x[(size_t)(b * 128 + c) * HW + hw0 + m];
        __nv_bfloat16 h = __float2bfloat16(v);
        __nv_bfloat16 l = __float2bfloat16(v - __bfloat162float(h));
        uint32_t off = sw_off(m, c);
        *(unsigned short*)(smem + SM_A_HI + off) = __bfloat16_as_ushort(h);
        *(unsigned short*)(smem + SM_A_LO + off) = __bfloat16_as_ushort(l);
    }
    __syncthreads();

    float acc[8][4];
#pragma unroll
    for (int j = 0; j < 8; j++)
#pragma unroll
        for (int q = 0; q < 4; q++) acc[j][q] = 0.f;

    const int m0 = (warp >> 1) * 16, n0 = (warp & 1) * 64;
    gemm_mma16(sb + SM_A_HI, sb + SM_A_LO, sb + SM_B_HI, sb + SM_B_LO, lane, m0, n0, acc);

#pragma unroll
    for (int ni = 0; ni < 8; ni++) {
        int row = m0 + (lane >> 2);
        int col = n0 + ni * 8 + (lane & 3) * 2;
        *(float2*)&g_xin[(size_t)(p0 + row) * 128 + col] =
            make_float2(acc[ni][0], acc[ni][1]);
        *(float2*)&g_xin[(size_t)(p0 + row + 8) * 128 + col] =
            make_float2(acc[ni][2], acc[ni][3]);
    }
}

// =====================================================================
// K2: depthwise 3x3 conv + bias + SiLU. WARP = 4 consecutive pixels.
// =====================================================================
__global__ void __launch_bounds__(256) k_dwsilu(const float* __restrict__ w,
                                                const float* __restrict__ bias) {
    __shared__ float sw[9 * 128];
    __shared__ float sb2[128];
    const int t = threadIdx.x;
    for (int i = t; i < 1152; i += 256) {
        int c = i / 9, k = i - c * 9;
        sw[k * 128 + c] = w[i];
    }
    if (t < 128) sb2[t] = bias[t];
    __syncthreads();

    const int warp = t >> 5, lane = t & 31, c0 = lane * 4;
    const int p0 = blockIdx.x * 32 + warp * 4;
    const int b = p0 >> 14, hw = p0 & 16383, yy = hw >> 7, xx0 = hw & 127;

    float4 bv = *(const float4*)&sb2[c0];
    float4 acc[4] = {bv, bv, bv, bv};
#pragma unroll
    for (int ky = 0; ky < 3; ky++) {
        int yv = yy + ky - 1;
        if ((unsigned)yv >= (unsigned)Hh) continue;
        const float* rowb = &g_xin[(size_t)(b * HW + yv * Wd) * Cn + c0];
        float4 v[6];
#pragma unroll
        for (int col = 0; col < 6; col++) {
            int xv = xx0 - 1 + col;
            v[col] = ((unsigned)xv < (unsigned)Wd) ? *(const float4*)&rowb[(size_t)xv * Cn]
                                                   : make_float4(0.f, 0.f, 0.f, 0.f);
        }
        float4 wv[3];
#pragma unroll
        for (int kx = 0; kx < 3; kx++) wv[kx] = *(const float4*)&sw[(ky * 3 + kx) * 128 + c0];
#pragma unroll
        for (int j = 0; j < 4; j++)
#pragma unroll
            for (int kx = 0; kx < 3; kx++) {
                float4 vv = v[j + kx];
                acc[j].x += wv[kx].x * vv.x; acc[j].y += wv[kx].y * vv.y;
                acc[j].z += wv[kx].z * vv.z; acc[j].w += wv[kx].w * vv.w;
            }
    }
#pragma unroll
    for (int j = 0; j < 4; j++) {
        float4 r;
        r.x = acc[j].x / (1.f + __expf(-acc[j].x));
        r.y = acc[j].y / (1.f + __expf(-acc[j].y));
        r.z = acc[j].z / (1.f + __expf(-acc[j].z));
        r.w = acc[j].w / (1.f + __expf(-acc[j].w));
        *(float4*)&g_xc[(size_t)(p0 + j) * Cn + c0] = r;
    }
}

__device__ __forceinline__ float softplusf(float x) {
    return fmaxf(x, 0.f) + log1pf(__expf(-fabsf(x)));
}

// =====================================================================
// K3: dwconv(dw_w) -> LN -> GELU -> offsets.  WARP = 4 pixels (R8 version).
// =====================================================================
__global__ void __launch_bounds__(256) k_dw2_off(const float* __restrict__ w,
                          const float* __restrict__ bias,
                          const float* __restrict__ lng, const float* __restrict__ lnb,
                          const float* __restrict__ offw, const float* __restrict__ offb) {
    __shared__ float sw[9 * 128];
    __shared__ float sb[128], sg[128], sbt[128];
    __shared__ float sofw[16 * 128];
    __shared__ float sofb[16];
    const int t = threadIdx.x;
    for (int i = t; i < 1152; i += 256) {
        int c = i / 9, k = i - c * 9;
        sw[k * 128 + c] = w[i];
    }
    for (int i = t; i < 2048; i += 256) sofw[i] = offw[i];
    if (t < 128) { sb[t] = bias[t]; sg[t] = lng[t]; sbt[t] = lnb[t]; }
    if (t < 16) sofb[t] = offb[t];
    __syncthreads();

    const int warp = t >> 5, lane = t & 31, c0 = lane * 4;
    const int p0 = blockIdx.x * 32 + warp * 4;
    const int b = p0 >> 14, hw = p0 & 16383, yy = hw >> 7, xx0 = hw & 127;

    // dwconv + bias, 4 pixels with horizontal tap reuse
    float4 bv = *(const float4*)&sb[c0];
    float4 acc[4] = {bv, bv, bv, bv};
#pragma unroll
    for (int ky = 0; ky < 3; ky++) {
        int yv = yy + ky - 1;
        if ((unsigned)yv >= (unsigned)Hh) continue;
        const float* rowb = &g_xc[(size_t)(b * HW + yv * Wd) * Cn + c0];
        float4 v[6];
#pragma unroll
        for (int col = 0; col < 6; col++) {
            int xv = xx0 - 1 + col;
            v[col] = ((unsigned)xv < (unsigned)Wd) ? *(const float4*)&rowb[(size_t)xv * Cn]
                                                   : make_float4(0.f, 0.f, 0.f, 0.f);
        }
        float4 wv[3];
#pragma unroll
        for (int kx = 0; kx < 3; kx++) wv[kx] = *(const float4*)&sw[(ky * 3 + kx) * 128 + c0];
#pragma unroll
        for (int j = 0; j < 4; j++)
#pragma unroll
            for (int kx = 0; kx < 3; kx++) {
                float4 vv = v[j + kx];
                acc[j].x += wv[kx].x * vv.x; acc[j].y += wv[kx].y * vv.y;
                acc[j].z += wv[kx].z * vv.z; acc[j].w += wv[kx].w * vv.w;
            }
    }

    const float4 gl = *(const float4*)&sg[c0];
    const float4 bl = *(const float4*)&sbt[c0];
    float u[4][4];
#pragma unroll
    for (int j = 0; j < 4; j++) {
        float s1 = acc[j].x + acc[j].y + acc[j].z + acc[j].w;
        float s2 = acc[j].x * acc[j].x + acc[j].y * acc[j].y
                 + acc[j].z * acc[j].z + acc[j].w * acc[j].w;
#pragma unroll
        for (int o = 16; o; o >>= 1) {
            s1 += __shfl_xor_sync(0xffffffffu, s1, o);
            s2 += __shfl_xor_sync(0xffffffffu, s2, o);
        }
        const float m = s1 * (1.f / 128.f);
        const float rs = rsqrtf(s2 * (1.f / 128.f) - m * m + 1e-6f);
        float xn0 = (acc[j].x - m) * rs * gl.x + bl.x;
        float xn1 = (acc[j].y - m) * rs * gl.y + bl.y;
        float xn2 = (acc[j].z - m) * rs * gl.z + bl.z;
        float xn3 = (acc[j].w - m) * rs * gl.w + bl.w;
        u[j][0] = 0.5f * xn0 * (1.f + erff(xn0 * 0.70710678118654752f));
        u[j][1] = 0.5f * xn1 * (1.f + erff(xn1 * 0.70710678118654752f));
        u[j][2] = 0.5f * xn2 * (1.f + erff(xn2 * 0.70710678118654752f));
        u[j][3] = 0.5f * xn3 * (1.f + erff(xn3 * 0.70710678118654752f));
    }

    // offsets per pixel (sequential to bound registers)
#pragma unroll
    for (int j = 0; j < 4; j++) {
        float oacc[16];
#pragma unroll
        for (int o = 0; o < 16; o++) {
            float4 wv = *(const float4*)&sofw[o * 128 + c0];
            oacc[o] = u[j][0] * wv.x + u[j][1] * wv.y + u[j][2] * wv.z + u[j][3] * wv.w;
        }
#pragma unroll
        for (int o = 16; o; o >>= 1)
#pragma unroll
            for (int q = 0; q < 16; q++)
                oacc[q] += __shfl_xor_sync(0xffffffffu, oacc[q], o);
        if (lane < 16) g_off[(p0 + j) * 16 + lane] = oacc[lane] + sofb[lane];
    }
}

// =====================================================================
// K4: DCNv3 sample + x_dbl + delta precompute.  WARP PER PIXEL.
// =====================================================================
__global__ void __launch_bounds__(256) k_dcn_delta(const float* __restrict__ xpw,
                            const float* __restrict__ dtw, const float* __restrict__ dtb,
                            const float* __restrict__ alog) {
    __shared__ float sxp[10 * 128];
    const int t = threadIdx.x;
    for (int i = t; i < 1280; i += 256) sxp[i] = xpw[i];
    __syncthreads();

    const int p = blockIdx.x * 8 + (t >> 5);
    const int lane = t & 31, c0 = lane * 4;
    const int b = p >> 14, hw = p & 16383, yy = hw >> 7, xx = hw & 127;
    const int g = lane >> 2;

    const float ox = g_off[p * 16 + 2 * g];
    const float oy = g_off[p * 16 + 2 * g + 1];
    const float px = (float)xx + ox, py = (float)yy + oy;
    const float x0 = floorf(px), y0 = floorf(py);
    const float wx = px - x0, wy = py - y0;
    float4 xd = make_float4(0.f, 0.f, 0.f, 0.f);
#pragma unroll
    for (int dy = 0; dy < 2; dy++) {
#pragma unroll
        for (int dx = 0; dx < 2; dx++) {
            float yif = y0 + (float)dy, xif = x0 + (float)dx;
            float wgt = (dy ? wy : 1.f - wy) * (dx ? wx : 1.f - wx);
            bool valid = (yif >= 0.f) && (yif < (float)Hh) && (xif >= 0.f) && (xif < (float)Wd);
            wgt = valid ? wgt : 0.f;
            int yi = (int)fminf(fmaxf(yif, 0.f), (float)(Hh - 1));
            int xi = (int)fminf(fmaxf(xif, 0.f), (float)(Wd - 1));
            float4 v = *(const float4*)&g_xc[(size_t)(b * HW + yi * Wd + xi) * Cn + c0];
            xd.x += v.x * wgt; xd.y += v.y * wgt; xd.z += v.z * wgt; xd.w += v.w * wgt;
        }
    }
    *(float4*)&g_xd[(size_t)p * Cn + c0] = xd;

    float xb[10];
#pragma unroll
    for (int r = 0; r < 10; r++) {
        float4 wv = *(const float4*)&sxp[r * 128 + c0];
        xb[r] = xd.x * wv.x + xd.y * wv.y + xd.z * wv.z + xd.w * wv.w;
    }
#pragma unroll
    for (int o = 16; o; o >>= 1)
#pragma unroll
        for (int j = 0; j < 10; j++)
            xb[j] += __shfl_xor_sync(0xffffffffu, xb[j], o);

    float av[4], bxv[4];
    float xdv[4] = {xd.x, xd.y, xd.z, xd.w};
#pragma unroll
    for (int j = 0; j < 4; j++) {
        int c = c0 + j;
        float4 w0 = *(const float4*)&dtw[c * 8];
        float4 w1 = *(const float4*)&dtw[c * 8 + 4];
        float dtr = __ldg(&dtb[c])
            + w0.x * xb[0] + w0.y * xb[1] + w0.z * xb[2] + w0.w * xb[3]
            + w1.x * xb[4] + w1.y * xb[5] + w1.z * xb[6] + w1.w * xb[7];
        float delta = softplusf(dtr);
        av[j] = __expf(-__expf(__ldg(&alog[c])) * delta);
        bxv[j] = delta * xb[8] * xdv[j];
    }
    *(float4*)&g_a [(size_t)p * Cn + c0] = make_float4(av[0], av[1], av[2], av[3]);
    *(float4*)&g_bx[(size_t)p * Cn + c0] = make_float4(bxv[0], bxv[1], bxv[2], bxv[3]);
    if (lane == 0) g_C[p] = xb[9];
}

// =====================================================================
// K5/K6/K7: chunked streaming scan
// =====================================================================
__global__ void k_scan1() {
    const int d = threadIdx.x;
    const int chunk = blockIdx.x, b = blockIdx.y;
    float Ar = 1.f, h = 0.f;
    size_t base = ((size_t)(b * HW + chunk * CL)) * Cn + d;
#pragma unroll 4
    for (int i = 0; i < CL; i++) {
        float a  = g_a [base + (size_t)i * Cn];
        float bx = g_bx[base + (size_t)i * Cn];
        Ar *= a;
        h = a * h + bx;
    }
    const int idx = (b * NCH + chunk) * Cn + d;
    g_As[idx] = Ar;
    g_Bs[idx] = h;
}

__global__ void k_scan2() {
    const int b = blockIdx.x, d = threadIdx.x;
    float h = 0.f;
#pragma unroll 4
    for (int ch = 0; ch < NCH; ch++) {
        const int idx = (b * NCH + ch) * Cn + d;
        g_hin[idx] = h;
        h = g_As[idx] * h + g_Bs[idx];
    }
}

__global__ void k_scan3(const float* __restrict__ Ds) {
    const int d = threadIdx.x;
    const int chunk = blockIdx.x, b = blockIdx.y;
    const float Dd = Ds[d];
    float h = g_hin[(b * NCH + chunk) * Cn + d];
    const int pbase = b * HW + chunk * CL;
    size_t base = (size_t)pbase * Cn + d;
#pragma unroll 4
    for (int i = 0; i < CL; i++) {
        float a  = g_a [base + (size_t)i * Cn];
        float bx = g_bx[base + (size_t)i * Cn];
        float xv = g_xd[base + (size_t)i * Cn];
        h = a * h + bx;
        g_y[base + (size_t)i * Cn] = h * g_C[pbase + i] + Dd * xv;
    }
}

// =====================================================================
// K8: out_proj GEMM. Warp-per-pixel LN directly from gmem (coalesced),
// writing bf16 hi/lo split into the swizzled A region.
// =====================================================================
__global__ void __launch_bounds__(512) k_out_proj(const float* __restrict__ lng,
                                                  const float* __restrict__ lnb,
                                                  float* __restrict__ out) {
    extern __shared__ char smem[];
    uint32_t sb = smem_to_u32(smem);
    const int t = threadIdx.x, lane = t & 31, warp = t >> 5;
    const int p0 = blockIdx.x * 128, b = p0 >> 14, hw0 = p0 & 16383;

    copy_weights_sw<512>(smem, g_wbhi_out, g_wblo_out, t);

    {
        const float4 gv = __ldg((const float4*)lng + lane);
        const float4 bv = __ldg((const float4*)lnb + lane);
#pragma unroll
        for (int j = 0; j < 8; j++) {
            int p = warp * 8 + j;
            float4 v = *(const float4*)&g_y[(size_t)(p0 + p) * 128 + lane * 4];
            float s1 = v.x + v.y + v.z + v.w;
            float s2 = v.x * v.x + v.y * v.y + v.z * v.z + v.w * v.w;
#pragma unroll
            for (int o = 16; o; o >>= 1) {
                s1 += __shfl_xor_sync(0xffffffffu, s1, o);
                s2 += __shfl_xor_sync(0xffffffffu, s2, o);
            }
            float m = s1 * (1.f / 128.f);
            float rs = rsqrtf(s2 * (1.f / 128.f) - m * m + 1e-6f);
            float a0 = (v.x - m) * rs * gv.x + bv.x;
            float a1 = (v.y - m) * rs * gv.y + bv.y;
            float a2 = (v.z - m) * rs * gv.z + bv.z;
            float a3 = (v.w - m) * rs * gv.w + bv.w;
            __nv_bfloat16 h0 = __float2bfloat16(a0), h1 = __float2bfloat16(a1);
            __nv_bfloat16 h2 = __float2bfloat16(a2), h3 = __float2bfloat16(a3);
            __nv_bfloat16 l0 = __float2bfloat16(a0 - __bfloat162float(h0));
            __nv_bfloat16 l1 = __float2bfloat16(a1 - __bfloat162float(h1));
            __nv_bfloat16 l2 = __float2bfloat16(a2 - __bfloat162float(h2));
            __nv_bfloat16 l3 = __float2bfloat16(a3 - __bfloat162float(h3));
            uint32_t off = sw_off(p, lane * 4);
            uint2 hp, lp;
            hp.x = (uint32_t)__bfloat16_as_ushort(h0) | ((uint32_t)__bfloat16_as_ushort(h1) << 16);
            hp.y = (uint32_t)__bfloat16_as_ushort(h2) | ((uint32_t)__bfloat16_as_ushort(h3) << 16);
            lp.x = (uint32_t)__bfloat16_as_ushort(l0) | ((uint32_t)__bfloat16_as_ushort(l1) << 16);
            lp.y = (uint32_t)__bfloat16_as_ushort(l2) | ((uint32_t)__bfloat16_as_ushort(l3) << 16);
            *(uint2*)(smem + SM_A_HI + off) = hp;
            *(uint2*)(smem + SM_A_LO + off) = lp;
        }
    }
    __syncthreads();

    float acc[8][4];
#pragma unroll
    for (int j = 0; j < 8; j++)
#pragma unroll
        for (int q = 0; q < 4; q++) acc[j][q] = 0.f;

    const int m0 = (warp >> 1) * 16, n0 = (warp & 1) * 64;
    gemm_mma16(sb + SM_A_HI, sb + SM_A_LO, sb + SM_B_HI, sb + SM_B_LO, lane, m0, n0, acc);

    __syncthreads();
    float* stg = (float*)smem;   // [128 outputs][132] pixels
#pragma unroll
    for (int ni = 0; ni < 8; ni++) {
        int row = m0 + (lane >> 2);
        int col = n0 + ni * 8 + (lane & 3) * 2;
        stg[(col)     * 132 + row]     = acc[ni][0];
        stg[(col + 1) * 132 + row]     = acc[ni][1];
        stg[(col)     * 132 + row + 8] = acc[ni][2];
        stg[(col + 1) * 132 + row + 8] = acc[ni][3];
    }
    __syncthreads();
    for (int i = t; i < 4096; i += 512) {
        int o = i >> 5, m4 = i & 31;
        float4 v4 = *(const float4*)&stg[o * 132 + m4 * 4];
        *(float4*)&out[(size_t)(b * 128 + o) * HW + hw0 + m4 * 4] = v4;
    }
}

// =====================================================================
extern "C" void kernel_launch(void* const* d_in, const int* in_sizes, int n_in,
                              void* d_out, int out_size) {
    const float* x      = (const float*)d_in[0];
    const float* inw    = (const float*)d_in[1];
    const float* c2w    = (const float*)d_in[2];
    const float* c2b    = (const float*)d_in[3];
    const float* dww    = (const float*)d_in[4];
    const float* dwb    = (const float*)d_in[5];
    const float* dlng   = (const float*)d_in[6];
    const float* dlnb   = (const float*)d_in[7];
    const float* offw   = (const float*)d_in[8];
    const float* offb   = (const float*)d_in[9];
    const float* xpw    = (const float*)d_in[10];
    const float* dtw    = (const float*)d_in[11];
    const float* dtb    = (const float*)d_in[12];
    const float* alog   = (const float*)d_in[13];
    const float* Ds     = (const float*)d_in[14];
    const float* olng   = (const float*)d_in[15];
    const float* olnb   = (const float*)d_in[16];
    const float* outw   = (const float*)d_in[17];
    float* out = (float*)d_out;

    cudaFuncSetAttribute(k_in_proj,  cudaFuncAttributeMaxDynamicSharedMemorySize, SM_GEMM);
    cudaFuncSetAttribute(k_out_proj, cudaFuncAttributeMaxDynamicSharedMemorySize, SM_GEMM);

    k_prep_in<<<64, 256>>>(inw);                    // 1
    k_prep_out<<<64, 256>>>(outw);                  // 2
    k_in_proj<<<P / 128, 512, SM_GEMM>>>(x);        // 3
    k_dwsilu<<<P / 32, 256>>>(c2w, c2b);            // 4  <- ncu slot
    k_dw2_off<<<P / 32, 256>>>(dww, dwb, dlng, dlnb, offw, offb); // 5
    k_dcn_delta<<<P / 8, 256>>>(xpw, dtw, dtb, alog);             // 6
    k_scan1<<<dim3(NCH, Bz), 128>>>();              // 7
    k_scan2<<<Bz, 128>>>();                         // 8
    k_scan3<<<dim3(NCH, Bz), 128>>>(Ds);            // 9
    k_out_proj<<<P / 128, 512, SM_GEMM>>>(olng, olnb, out);       // 10
}